// round 17
// baseline (speedup 1.0000x reference)
#include <cuda_runtime.h>
#include <cstdint>

#define VOCAB 67
#define EMB 50
#define NLAYERS 8
#define REP_FLOATS 4824       // 67 rows * 72 floats
#define TAB_FLOATS (4*REP_FLOATS)
#define GRID 2048

// Precomputed per-token logits, stored as 4 shifted replicas:
// replica j stores row element e at padded position e + pad_j (pads 0,3,2,1), rows 72 floats.
__device__ __align__(16) float g_tab[TAB_FLOATS];
__device__ int g_count;   // table-rows-done counter (self-resetting)
__device__ int g_exit;    // block-exit counter     (self-resetting)

__device__ __forceinline__ void stcs128(float4* p, float4 v) {
    asm volatile("st.global.cs.v4.f32 [%0], {%1,%2,%3,%4};"
                 :: "l"(p), "f"(v.x), "f"(v.y), "f"(v.z), "f"(v.w) : "memory");
}

// ---------------------------------------------------------------------------
// Fused kernel, LOW-SMEM (~1.3 KB): R11's fusion failed because 41KB static
// smem x 5 resident blocks = 205KB carveout left L1D at 23KB, evicting the
// 77KB table -> every gather read was an L2 hit. Here the table phase reads
// weights directly via coalesced __ldg (160KB total, L1-resident across the
// 67 table blocks), so the carveout stays ~5KB and the gather phase keeps
// the table in L1.
// ---------------------------------------------------------------------------
__global__ void __launch_bounds__(256, 4) fused_kernel(
    const int*   __restrict__ idx,    // [64*8192]
    const float* __restrict__ emb,    // [67,50]
    const float* __restrict__ kappa,  // [8,50,50]
    const float* __restrict__ phi,    // [8,50,50]
    const float* __restrict__ W_out,  // [50,67]
    const float* __restrict__ b_out,  // [67]
    float*       __restrict__ out)
{
    __shared__ float sar[2][EMB], sai[2][EMB], sint[EMB];   // ~1.3 KB

    const int tid  = threadIdx.x;
    const int b    = blockIdx.x;
    const int lane = tid & 31;
    const int warp = b * 8 + (tid >> 5);                 // 0..16383

    // ---- gather prologue FIRST: overlaps the table phase / spin ----
    const int mytok = __ldg(idx + warp*32 + lane);       // token ids < 67
    const int nx    = __shfl_down_sync(0xffffffffu, mytok, 1);
    const int pair  = mytok | (nx << 8);                 // {tok[lane], tok[lane+1]}
    float4* O = (float4*)out + (uint32_t)warp * 536;

    // ---------------- phase 1: table (blocks 0..66 only) ----------------
    if (b < VOCAB) {
        const int t = b;
        // threads 0..49 -> real component f=tid; threads 128..177 -> imag f=tid-128
        const int part = tid >> 7;          // 0 = real half, 1 = imag half
        const int f    = tid & 127;

        if (tid < EMB) { sar[0][tid] = __ldg(emb + t*EMB + tid); sai[0][tid] = 0.f; }
        __syncthreads();

        for (int l = 0; l < NLAYERS; ++l) {
            const int cur = l & 1, nxt = cur ^ 1;
            const float* K = kappa + l*EMB*EMB;
            const float* P = phi   + l*EMB*EMB;
            if (f < EMB) {
                if (part == 0) {
                    float a0=0.f, a1=0.f;
                    #pragma unroll 10
                    for (int e = 0; e < EMB; e += 2) {
                        a0 += sar[cur][e+0]*__ldg(K+(e+0)*EMB+f) - sai[cur][e+0]*__ldg(P+(e+0)*EMB+f);
                        a1 += sar[cur][e+1]*__ldg(K+(e+1)*EMB+f) - sai[cur][e+1]*__ldg(P+(e+1)*EMB+f);
                    }
                    sar[nxt][f] = a0 + a1;
                } else {
                    float a0=0.f, a1=0.f;
                    #pragma unroll 10
                    for (int e = 0; e < EMB; e += 2) {
                        a0 += sar[cur][e+0]*__ldg(P+(e+0)*EMB+f) + sai[cur][e+0]*__ldg(K+(e+0)*EMB+f);
                        a1 += sar[cur][e+1]*__ldg(P+(e+1)*EMB+f) + sai[cur][e+1]*__ldg(K+(e+1)*EMB+f);
                    }
                    sai[nxt][f] = a0 + a1;
                }
            }
            __syncthreads();
        }

        if (tid < EMB) {                     // 8 layers (even): buffer 0
            float a = sar[0][tid], c = sai[0][tid];
            sint[tid] = a*a + c*c;
        }
        __syncthreads();
        if (tid < VOCAB) {
            float acc = __ldg(b_out + tid);
            #pragma unroll 10
            for (int e = 0; e < EMB; ++e)
                acc += sint[e] * __ldg(W_out + e*VOCAB + tid);
            g_tab[0*REP_FLOATS + t*72 + tid + 0] = acc;
            g_tab[1*REP_FLOATS + t*72 + tid + 3] = acc;
            g_tab[2*REP_FLOATS + t*72 + tid + 2] = acc;
            g_tab[3*REP_FLOATS + t*72 + tid + 1] = acc;
        }
        __syncthreads();                     // all row writes issued
        __threadfence();                     // release
        if (tid == 0) atomicAdd(&g_count, 1);
    }

    // ---------------- barrier: wait for all 67 table rows ----------------
    if (tid == 0) {
        while (*(volatile int*)&g_count < VOCAB) __nanosleep(64);
    }
    __syncthreads();
    __threadfence();                         // acquire

    // ---------------- phase 2: gather (byte-exact verified R7 body) ----------------
    #pragma unroll
    for (int i = 0; i < 17; ++i) {
        const int p4 = lane + 32*i;          // output float4 index
        const int e0 = 4*p4;
        const int tk = (int)((unsigned)e0 / 67u);  // owning token slot
        const int r  = e0 - 67*tk;           // element offset within token row

        const int pp     = __shfl_sync(0xffffffffu, pair, tk & 31);
        const int token  = pp & 0xff;
        const int token2 = (pp >> 8) & 0xff;

        const int j   = tk & 3;              // == r & 3 (e0 % 4 == 0)
        const int pos = (r + 3) & ~3;        // r + pad_j, 16B-aligned
        float4 v = __ldg((const float4*)(g_tab + j*REP_FLOATS + token*72 + pos));

        if (r >= 64) {                       // straddle: tail from next token
            float4 w = __ldg((const float4*)(g_tab + (j+1)*REP_FLOATS + token2*72));
            if (r == 66) v.y = w.y;
            if (r >= 65) v.z = w.z;
            v.w = w.w;
        }
        if (i < 16 || lane < 24)             // quads >=536 don't exist
            stcs128(O + p4, v);
    }

    // ---------------- exit: last block resets counters ----------------
    __syncthreads();
    if (tid == 0) {
        int old = atomicAdd(&g_exit, 1);
        if (old == (int)gridDim.x - 1) {     // clean state for next replay
            g_count = 0;
            g_exit  = 0;
        }
    }
}

// ---------------------------------------------------------------------------
// Launch: ONE kernel (saves a graph-node launch + inter-kernel gap).
// ---------------------------------------------------------------------------
extern "C" void kernel_launch(void* const* d_in, const int* in_sizes, int n_in,
                              void* d_out, int out_size) {
    const int*   idx = (const int*)d_in[0];   // input_seq [64,8192] int32
    const float* emb = (const float*)d_in[1]; // embedding_table [67,50]
    const float* kap = (const float*)d_in[2]; // kappa [8,50,50]
    const float* ph  = (const float*)d_in[3]; // phi   [8,50,50]
    const float* Wo  = (const float*)d_in[4]; // W_out [50,67]
    const float* bo  = (const float*)d_in[5]; // b_out [67]
    float* out = (float*)d_out;

    fused_kernel<<<GRID, 256>>>(idx, emb, kap, ph, Wo, bo, out);
}